// round 4
// baseline (speedup 1.0000x reference)
#include <cuda_runtime.h>
#include <cuda_bf16.h>
#include <cstdint>

// NPSCalculator: nps = sum_{b,h,w} min_k sqrt( sum_c (x[b,c,h,w] - p[k,c] + 1e-6)^2 + 1e-6 ) / size
// B=8, C=3, H=512, W=512, NUM_COLORS=30.
//
// R4: shared-crossbar-bandwidth attack. R3 evidence: L1=49% top unit, dur invariant to
// occupancy and fma changes -> LDS.128 of warp-uniform addresses is NOT broadcast-dedup'd
// (512B crossbar per access). Fix: amortize each color fetch over 8 pixels (4 packed
// pairs), halving crossbar bytes/pixel: 503MB -> 252MB (~13.3K cyc floor).
//  - dist^2 = ssq_pixel + (2v)·x + sum v^2 ; min over colors before the single sqrt.
//  - 2048 blocks x 128 threads, launch_bounds(128,8): 8 blocks/SM, small drain tail.
//  - 4 independent FFMA2 chains per color iteration (ILP 4).
//  - single launch: per-block partials + wrap-around atomicInc last-block reduce.

#define HW_       262144
#define CHW_      (3 * HW_)
#define THREADS_  128
#define BLOCKS_   2048
#define NTHR_     (THREADS_ * BLOCKS_)    // 262144 threads
#define INV_SIZE_ (1.0f / 6291456.0f)

typedef unsigned long long u64;

__device__ float        g_partial[BLOCKS_];
__device__ unsigned int g_count = 0;

__device__ __forceinline__ u64 f2pk(float lo, float hi) {
    u64 r; asm("mov.b64 %0, {%1, %2};" : "=l"(r) : "f"(lo), "f"(hi)); return r;
}
__device__ __forceinline__ void f2unpk(u64 v, float& lo, float& hi) {
    asm("mov.b64 {%0, %1}, %2;" : "=f"(lo), "=f"(hi) : "l"(v));
}
__device__ __forceinline__ u64 fma2(u64 a, u64 b, u64 c) {
    u64 r; asm("fma.rn.f32x2 %0, %1, %2, %3;" : "=l"(r) : "l"(a), "l"(b), "l"(c)); return r;
}
// fused: {lo,hi} = a*b + c  (unpack aliased by ptxas, no extra SASS movs)
__device__ __forceinline__ void fma2u(u64 a, u64 b, u64 c, float& lo, float& hi) {
    asm("{\n\t.reg .b64 t;\n\tfma.rn.f32x2 t, %2, %3, %4;\n\tmov.b64 {%0, %1}, t;\n\t}"
        : "=f"(lo), "=f"(hi) : "l"(a), "l"(b), "l"(c));
}

__global__ __launch_bounds__(THREADS_, 8)
void nps_kernel(const float* __restrict__ adv,
                const float* __restrict__ prn,
                float* __restrict__ out)
{
    // [k][0] = {W0, W1}, [k][1] = {W2, C};  W_c = 2*(1e-6 - p_kc) dup'd, C = sum v^2 dup'd
    __shared__ ulonglong2 shWC[60];
    __shared__ float      shRed[4];
    __shared__ int        shLast;

    int tid = threadIdx.x;
    if (tid < 30) {
        float v0 = 1e-6f - prn[tid * 3 + 0];
        float v1 = 1e-6f - prn[tid * 3 + 1];
        float v2 = 1e-6f - prn[tid * 3 + 2];
        float c  = v0 * v0 + v1 * v1 + v2 * v2;
        shWC[tid * 2 + 0] = make_ulonglong2(f2pk(2.f * v0, 2.f * v0),
                                            f2pk(2.f * v1, 2.f * v1));
        shWC[tid * 2 + 1] = make_ulonglong2(f2pk(2.f * v2, 2.f * v2),
                                            f2pk(c, c));
    }
    __syncthreads();

    // two float4-groups (8 pixels) per thread; stride NTHR_ groups for coalescing
    int tglob = blockIdx.x * THREADS_ + tid;       // 0 .. 262143
    float4 a0, a1, a2, b0, b1, b2;
    {
        int p4 = tglob * 4;
        const float4* q = reinterpret_cast<const float4*>(
            adv + (size_t)(p4 >> 18) * CHW_ + (p4 & (HW_ - 1)));
        a0 = q[0]; a1 = q[HW_ / 4]; a2 = q[2 * (HW_ / 4)];
    }
    {
        int p4 = (tglob + NTHR_) * 4;
        const float4* q = reinterpret_cast<const float4*>(
            adv + (size_t)(p4 >> 18) * CHW_ + (p4 & (HW_ - 1)));
        b0 = q[0]; b1 = q[HW_ / 4]; b2 = q[2 * (HW_ / 4)];
    }

    // 4 pixel-pairs (A,B from group0; C,D from group1)
    u64 XA0 = f2pk(a0.x, a0.y), XA1 = f2pk(a1.x, a1.y), XA2 = f2pk(a2.x, a2.y);
    u64 XB0 = f2pk(a0.z, a0.w), XB1 = f2pk(a1.z, a1.w), XB2 = f2pk(a2.z, a2.w);
    u64 XC0 = f2pk(b0.x, b0.y), XC1 = f2pk(b1.x, b1.y), XC2 = f2pk(b2.x, b2.y);
    u64 XD0 = f2pk(b0.z, b0.w), XD1 = f2pk(b1.z, b1.w), XD2 = f2pk(b2.z, b2.w);

    const u64 EPS2 = f2pk(1e-6f, 1e-6f);
    // per-pixel sum of squares + 1e-6 (constant over colors)
    u64 sA = fma2(XA0, XA0, EPS2); sA = fma2(XA1, XA1, sA); sA = fma2(XA2, XA2, sA);
    u64 sB = fma2(XB0, XB0, EPS2); sB = fma2(XB1, XB1, sB); sB = fma2(XB2, XB2, sB);
    u64 sC = fma2(XC0, XC0, EPS2); sC = fma2(XC1, XC1, sC); sC = fma2(XC2, XC2, sC);
    u64 sD = fma2(XD0, XD0, EPS2); sD = fma2(XD1, XD1, sD); sD = fma2(XD2, XD2, sD);

    float mA0, mA1, mB0, mB1, mC0, mC1, mD0, mD1;
    {   // k = 0 peeled: initializes the mins
        ulonglong2 w01 = shWC[0];
        ulonglong2 w2c = shWC[1];
        u64 aA = fma2(w01.x, XA0, w2c.y);
        u64 aB = fma2(w01.x, XB0, w2c.y);
        u64 aC = fma2(w01.x, XC0, w2c.y);
        u64 aD = fma2(w01.x, XD0, w2c.y);
        aA = fma2(w01.y, XA1, aA); aB = fma2(w01.y, XB1, aB);
        aC = fma2(w01.y, XC1, aC); aD = fma2(w01.y, XD1, aD);
        fma2u(w2c.x, XA2, aA, mA0, mA1);
        fma2u(w2c.x, XB2, aB, mB0, mB1);
        fma2u(w2c.x, XC2, aC, mC0, mC1);
        fma2u(w2c.x, XD2, aD, mD0, mD1);
    }

    #pragma unroll 29
    for (int k = 1; k < 30; k++) {
        ulonglong2 w01 = shWC[k * 2 + 0];
        ulonglong2 w2c = shWC[k * 2 + 1];
        float lo, hi;
        u64 aA = fma2(w01.x, XA0, w2c.y);
        u64 aB = fma2(w01.x, XB0, w2c.y);
        u64 aC = fma2(w01.x, XC0, w2c.y);
        u64 aD = fma2(w01.x, XD0, w2c.y);
        aA = fma2(w01.y, XA1, aA); aB = fma2(w01.y, XB1, aB);
        aC = fma2(w01.y, XC1, aC); aD = fma2(w01.y, XD1, aD);
        fma2u(w2c.x, XA2, aA, lo, hi); mA0 = fminf(mA0, lo); mA1 = fminf(mA1, hi);
        fma2u(w2c.x, XB2, aB, lo, hi); mB0 = fminf(mB0, lo); mB1 = fminf(mB1, hi);
        fma2u(w2c.x, XC2, aC, lo, hi); mC0 = fminf(mC0, lo); mC1 = fminf(mC1, hi);
        fma2u(w2c.x, XD2, aD, lo, hi); mD0 = fminf(mD0, lo); mD1 = fminf(mD1, hi);
    }

    float l0, h0, l1, h1, l2, h2, l3, h3;
    f2unpk(sA, l0, h0); f2unpk(sB, l1, h1);
    f2unpk(sC, l2, h2); f2unpk(sD, l3, h3);

    float tsum = sqrtf(mA0 + l0) + sqrtf(mA1 + h0)
               + sqrtf(mB0 + l1) + sqrtf(mB1 + h1)
               + sqrtf(mC0 + l2) + sqrtf(mC1 + h2)
               + sqrtf(mD0 + l3) + sqrtf(mD1 + h3);

    // warp reduce
    #pragma unroll
    for (int off = 16; off > 0; off >>= 1)
        tsum += __shfl_xor_sync(0xffffffffu, tsum, off);
    if ((tid & 31) == 0) shRed[tid >> 5] = tsum;
    __syncthreads();

    if (tid == 0) {
        float bs = shRed[0] + shRed[1] + shRed[2] + shRed[3];
        g_partial[blockIdx.x] = bs;
        __threadfence();
        unsigned int prev = atomicInc(&g_count, BLOCKS_ - 1);
        shLast = (prev == BLOCKS_ - 1);
    }
    __syncthreads();

    if (shLast) {
        volatile float* vp = g_partial;
        float s = 0.0f;
        #pragma unroll
        for (int i = 0; i < BLOCKS_ / THREADS_; i++)
            s += vp[tid + i * THREADS_];
        #pragma unroll
        for (int off = 16; off > 0; off >>= 1)
            s += __shfl_xor_sync(0xffffffffu, s, off);
        if ((tid & 31) == 0) shRed[tid >> 5] = s;
        __syncthreads();
        if (tid == 0)
            out[0] = (shRed[0] + shRed[1] + shRed[2] + shRed[3]) * INV_SIZE_;
    }
}

extern "C" void kernel_launch(void* const* d_in, const int* in_sizes, int n_in,
                              void* d_out, int out_size)
{
    const float* adv = (const float*)d_in[0];   // (8,3,512,512) f32
    const float* prn = (const float*)d_in[1];   // (30,3) f32
    nps_kernel<<<BLOCKS_, THREADS_>>>(adv, prn, (float*)d_out);
}

// round 5
// speedup vs baseline: 1.1175x; 1.1175x over previous
#include <cuda_runtime.h>
#include <cuda_bf16.h>
#include <cstdint>

// NPSCalculator: nps = sum_{b,h,w} min_k sqrt( sum_c (x[b,c,h,w] - p[k,c] + 1e-6)^2 + 1e-6 ) / size
// B=8, C=3, H=512, W=512, NUM_COLORS=30.
//
// R5: kill the MUFU bottleneck. R1-R4 all pinned at ~17-19us across wildly different
// configs; the invariant is 2.097M sqrtf = 2.097M MUFU ops = 2.097M/(148*0.5/cyc)
// = 28.3K cycles -- exactly the measured duration. sqrt is now computed MUFU-free:
// integer rsqrt seed (0x5f3759df - (i>>1), pure ALU; x in [2e-6,13] so always valid)
// + 2 packed f32x2 Newton iterations (rel err ~5e-6, well under 1e-3) + x*r.
//  - dist^2 = ssq_pixel + (2v)·x + sum v^2 ; min over colors before the sqrt.
//  - 8 px/thread, 2048 blocks x 128 threads, 4 independent packed chains.
//  - single launch: per-block partials + wrap-around atomicInc last-block reduce.

#define HW_       262144
#define CHW_      (3 * HW_)
#define THREADS_  128
#define BLOCKS_   2048
#define NTHR_     (THREADS_ * BLOCKS_)    // 262144 threads
#define INV_SIZE_ (1.0f / 6291456.0f)

typedef unsigned long long u64;

__device__ float        g_partial[BLOCKS_];
__device__ unsigned int g_count = 0;

__device__ __forceinline__ u64 f2pk(float lo, float hi) {
    u64 r; asm("mov.b64 %0, {%1, %2};" : "=l"(r) : "f"(lo), "f"(hi)); return r;
}
__device__ __forceinline__ void f2unpk(u64 v, float& lo, float& hi) {
    asm("mov.b64 {%0, %1}, %2;" : "=f"(lo), "=f"(hi) : "l"(v));
}
__device__ __forceinline__ u64 fma2(u64 a, u64 b, u64 c) {
    u64 r; asm("fma.rn.f32x2 %0, %1, %2, %3;" : "=l"(r) : "l"(a), "l"(b), "l"(c)); return r;
}
__device__ __forceinline__ u64 mul2(u64 a, u64 b) {
    u64 r; asm("mul.rn.f32x2 %0, %1, %2;" : "=l"(r) : "l"(a), "l"(b)); return r;
}
__device__ __forceinline__ u64 add2(u64 a, u64 b) {
    u64 r; asm("add.rn.f32x2 %0, %1, %2;" : "=l"(r) : "l"(a), "l"(b)); return r;
}
// fused: {lo,hi} = a*b + c  (unpack aliased by ptxas)
__device__ __forceinline__ void fma2u(u64 a, u64 b, u64 c, float& lo, float& hi) {
    asm("{\n\t.reg .b64 t;\n\tfma.rn.f32x2 t, %2, %3, %4;\n\tmov.b64 {%0, %1}, t;\n\t}"
        : "=f"(lo), "=f"(hi) : "l"(a), "l"(b), "l"(c));
}

// MUFU-free packed sqrt of {lo,hi}: magic rsqrt seed + 2 Newton iters + x*r.
// Valid for x in [~1e-30, 1e30] positive normals; here x in [2e-6, ~13].
__device__ __forceinline__ u64 sqrt2_nomufu(u64 x, u64 C_H, u64 C_1p5) {
    float xl, xh;
    f2unpk(x, xl, xh);
    float rl = __int_as_float(0x5f3759df - (__float_as_int(xl) >> 1));
    float rh = __int_as_float(0x5f3759df - (__float_as_int(xh) >> 1));
    u64 r   = f2pk(rl, rh);
    u64 hxn = mul2(x, C_H);                 // -0.5 * x
    u64 m, u;
    m = mul2(r, r); u = fma2(hxn, m, C_1p5); r = mul2(r, u);   // iter 1
    m = mul2(r, r); u = fma2(hxn, m, C_1p5); r = mul2(r, u);   // iter 2
    return mul2(x, r);                      // sqrt(x) = x * rsqrt(x)
}

__global__ __launch_bounds__(THREADS_, 8)
void nps_kernel(const float* __restrict__ adv,
                const float* __restrict__ prn,
                float* __restrict__ out)
{
    // [k][0] = {W0, W1}, [k][1] = {W2, C};  W_c = 2*(1e-6 - p_kc) dup'd, C = sum v^2 dup'd
    __shared__ ulonglong2 shWC[60];
    __shared__ float      shRed[4];
    __shared__ int        shLast;

    int tid = threadIdx.x;
    if (tid < 30) {
        float v0 = 1e-6f - prn[tid * 3 + 0];
        float v1 = 1e-6f - prn[tid * 3 + 1];
        float v2 = 1e-6f - prn[tid * 3 + 2];
        float c  = v0 * v0 + v1 * v1 + v2 * v2;
        shWC[tid * 2 + 0] = make_ulonglong2(f2pk(2.f * v0, 2.f * v0),
                                            f2pk(2.f * v1, 2.f * v1));
        shWC[tid * 2 + 1] = make_ulonglong2(f2pk(2.f * v2, 2.f * v2),
                                            f2pk(c, c));
    }
    __syncthreads();

    // two float4-groups (8 pixels) per thread; stride NTHR_ groups for coalescing
    int tglob = blockIdx.x * THREADS_ + tid;       // 0 .. 262143
    float4 a0, a1, a2, b0, b1, b2;
    {
        int p4 = tglob * 4;
        const float4* q = reinterpret_cast<const float4*>(
            adv + (size_t)(p4 >> 18) * CHW_ + (p4 & (HW_ - 1)));
        a0 = q[0]; a1 = q[HW_ / 4]; a2 = q[2 * (HW_ / 4)];
    }
    {
        int p4 = (tglob + NTHR_) * 4;
        const float4* q = reinterpret_cast<const float4*>(
            adv + (size_t)(p4 >> 18) * CHW_ + (p4 & (HW_ - 1)));
        b0 = q[0]; b1 = q[HW_ / 4]; b2 = q[2 * (HW_ / 4)];
    }

    // 4 pixel-pairs (A,B from group0; C,D from group1)
    u64 XA0 = f2pk(a0.x, a0.y), XA1 = f2pk(a1.x, a1.y), XA2 = f2pk(a2.x, a2.y);
    u64 XB0 = f2pk(a0.z, a0.w), XB1 = f2pk(a1.z, a1.w), XB2 = f2pk(a2.z, a2.w);
    u64 XC0 = f2pk(b0.x, b0.y), XC1 = f2pk(b1.x, b1.y), XC2 = f2pk(b2.x, b2.y);
    u64 XD0 = f2pk(b0.z, b0.w), XD1 = f2pk(b1.z, b1.w), XD2 = f2pk(b2.z, b2.w);

    const u64 EPS2 = f2pk(1e-6f, 1e-6f);
    // per-pixel sum of squares + 1e-6 (constant over colors)
    u64 sA = fma2(XA0, XA0, EPS2); sA = fma2(XA1, XA1, sA); sA = fma2(XA2, XA2, sA);
    u64 sB = fma2(XB0, XB0, EPS2); sB = fma2(XB1, XB1, sB); sB = fma2(XB2, XB2, sB);
    u64 sC = fma2(XC0, XC0, EPS2); sC = fma2(XC1, XC1, sC); sC = fma2(XC2, XC2, sC);
    u64 sD = fma2(XD0, XD0, EPS2); sD = fma2(XD1, XD1, sD); sD = fma2(XD2, XD2, sD);

    float mA0, mA1, mB0, mB1, mC0, mC1, mD0, mD1;
    {   // k = 0 peeled: initializes the mins
        ulonglong2 w01 = shWC[0];
        ulonglong2 w2c = shWC[1];
        u64 aA = fma2(w01.x, XA0, w2c.y);
        u64 aB = fma2(w01.x, XB0, w2c.y);
        u64 aC = fma2(w01.x, XC0, w2c.y);
        u64 aD = fma2(w01.x, XD0, w2c.y);
        aA = fma2(w01.y, XA1, aA); aB = fma2(w01.y, XB1, aB);
        aC = fma2(w01.y, XC1, aC); aD = fma2(w01.y, XD1, aD);
        fma2u(w2c.x, XA2, aA, mA0, mA1);
        fma2u(w2c.x, XB2, aB, mB0, mB1);
        fma2u(w2c.x, XC2, aC, mC0, mC1);
        fma2u(w2c.x, XD2, aD, mD0, mD1);
    }

    #pragma unroll 29
    for (int k = 1; k < 30; k++) {
        ulonglong2 w01 = shWC[k * 2 + 0];
        ulonglong2 w2c = shWC[k * 2 + 1];
        float lo, hi;
        u64 aA = fma2(w01.x, XA0, w2c.y);
        u64 aB = fma2(w01.x, XB0, w2c.y);
        u64 aC = fma2(w01.x, XC0, w2c.y);
        u64 aD = fma2(w01.x, XD0, w2c.y);
        aA = fma2(w01.y, XA1, aA); aB = fma2(w01.y, XB1, aB);
        aC = fma2(w01.y, XC1, aC); aD = fma2(w01.y, XD1, aD);
        fma2u(w2c.x, XA2, aA, lo, hi); mA0 = fminf(mA0, lo); mA1 = fminf(mA1, hi);
        fma2u(w2c.x, XB2, aB, lo, hi); mB0 = fminf(mB0, lo); mB1 = fminf(mB1, hi);
        fma2u(w2c.x, XC2, aC, lo, hi); mC0 = fminf(mC0, lo); mC1 = fminf(mC1, hi);
        fma2u(w2c.x, XD2, aD, lo, hi); mD0 = fminf(mD0, lo); mD1 = fminf(mD1, hi);
    }

    // dist^2 per pixel (packed) = packed mins + packed ssq
    u64 dA = add2(f2pk(mA0, mA1), sA);
    u64 dB = add2(f2pk(mB0, mB1), sB);
    u64 dC = add2(f2pk(mC0, mC1), sC);
    u64 dD = add2(f2pk(mD0, mD1), sD);

    // MUFU-free packed sqrt (4 independent chains)
    const u64 C_H   = f2pk(-0.5f, -0.5f);
    const u64 C_1p5 = f2pk(1.5f, 1.5f);
    u64 qA = sqrt2_nomufu(dA, C_H, C_1p5);
    u64 qB = sqrt2_nomufu(dB, C_H, C_1p5);
    u64 qC = sqrt2_nomufu(dC, C_H, C_1p5);
    u64 qD = sqrt2_nomufu(dD, C_H, C_1p5);

    u64 t0 = add2(qA, qB);
    u64 t1 = add2(qC, qD);
    u64 ts = add2(t0, t1);
    float tl, th;
    f2unpk(ts, tl, th);
    float tsum = tl + th;

    // warp reduce
    #pragma unroll
    for (int off = 16; off > 0; off >>= 1)
        tsum += __shfl_xor_sync(0xffffffffu, tsum, off);
    if ((tid & 31) == 0) shRed[tid >> 5] = tsum;
    __syncthreads();

    if (tid == 0) {
        float bs = shRed[0] + shRed[1] + shRed[2] + shRed[3];
        g_partial[blockIdx.x] = bs;
        __threadfence();
        unsigned int prev = atomicInc(&g_count, BLOCKS_ - 1);
        shLast = (prev == BLOCKS_ - 1);
    }
    __syncthreads();

    if (shLast) {
        volatile float* vp = g_partial;
        float s = 0.0f;
        #pragma unroll
        for (int i = 0; i < BLOCKS_ / THREADS_; i++)
            s += vp[tid + i * THREADS_];
        #pragma unroll
        for (int off = 16; off > 0; off >>= 1)
            s += __shfl_xor_sync(0xffffffffu, s, off);
        if ((tid & 31) == 0) shRed[tid >> 5] = s;
        __syncthreads();
        if (tid == 0)
            out[0] = (shRed[0] + shRed[1] + shRed[2] + shRed[3]) * INV_SIZE_;
    }
}

extern "C" void kernel_launch(void* const* d_in, const int* in_sizes, int n_in,
                              void* d_out, int out_size)
{
    const float* adv = (const float*)d_in[0];   // (8,3,512,512) f32
    const float* prn = (const float*)d_in[1];   // (30,3) f32
    nps_kernel<<<BLOCKS_, THREADS_>>>(adv, prn, (float*)d_out);
}